// round 15
// baseline (speedup 1.0000x reference)
#include <cuda_runtime.h>
#include <cuda_bf16.h>
#include <cstddef>
#include <cstdint>

#define Nb 64
#define Ts 512
#define Dd 1024
#define Hh 1024
#define Gg 4096   // 4*Hh

typedef unsigned long long u64;
typedef __nv_bfloat16 bf16;

// Scratch (static device arrays; no allocations).
__device__ float g_xw[(size_t)Nb * Ts * Gg];     // (t, n, 4H)
__device__ int   g_flagc[128];                   // per-CTA monotonic publish counters

// h state for the recurrence, bf16 hi/lo split, [n][k] layout, double-buffered.
__device__ __align__(16) bf16 g_hbh[2][Nb * Hh];
__device__ __align__(16) bf16 g_hbl[2][Nb * Hh];

// bf16-split operands for the tensor-core input GEMM.
__device__ __align__(16) bf16 g_Ah[(size_t)Nb * Ts * Dd];  // A hi [m][d], m=t*64+n
__device__ __align__(16) bf16 g_Al[(size_t)Nb * Ts * Dd];  // A lo
__device__ __align__(16) bf16 g_Bh[(size_t)Gg * Dd];       // Wx^T hi [g][d]
__device__ __align__(16) bf16 g_Bl[(size_t)Gg * Dd];       // Wx^T lo

__device__ __forceinline__ void cp16(void* smem, const void* g) {
    unsigned saddr = (unsigned)__cvta_generic_to_shared(smem);
    asm volatile("cp.async.cg.shared.global [%0], [%1], 16;" :: "r"(saddr), "l"(g));
}
#define CP_COMMIT() asm volatile("cp.async.commit_group;")
#define CP_WAIT1()  asm volatile("cp.async.wait_group 1;")
#define CP_WAIT2()  asm volatile("cp.async.wait_group 2;")

// mma.sync m16n8k16 row.col f32.bf16.bf16.f32 — baseline PTX (works on compute_103).
#define MMA16816(c, a0, a1, a2, a3, b0, b1) \
    asm volatile("mma.sync.aligned.m16n8k16.row.col.f32.bf16.bf16.f32 " \
                 "{%0,%1,%2,%3}, {%4,%5,%6,%7}, {%8,%9}, {%0,%1,%2,%3};" \
                 : "+f"((c)[0]), "+f"((c)[1]), "+f"((c)[2]), "+f"((c)[3]) \
                 : "r"(a0), "r"(a1), "r"(a2), "r"(a3), "r"(b0), "r"(b1))

// ===================================================================
// prep: zero per-CTA flags; convert h0 -> bf16 hi/lo [n][k]
// ===================================================================
__global__ void prep(const float* __restrict__ h0) {
    int tid = blockIdx.x * blockDim.x + threadIdx.x;
    int nt  = gridDim.x * blockDim.x;
    if (tid < 128) g_flagc[tid] = 0;
    for (int i = tid; i < Nb * Hh; i += nt) {
        float v = h0[i];
        bf16 hh = __float2bfloat16(v);
        g_hbh[0][i] = hh;
        g_hbl[0][i] = __float2bfloat16(v - __bfloat162float(hh));
    }
}

// ===================================================================
// conv_x: x (N,T,D) fp32 -> bf16 hi/lo rows m = t*64+n.
// ===================================================================
__global__ void conv_x(const float* __restrict__ x) {
    size_t u = (size_t)blockIdx.x * blockDim.x + threadIdx.x;
    int m  = (int)(u >> 7);
    int d0 = (int)(u & 127) << 3;
    int t = m >> 6, n = m & 63;
    const float* src = x + ((size_t)n * Ts + t) * Dd + d0;
    float4 v0 = *(const float4*)src;
    float4 v1 = *(const float4*)(src + 4);
    float vv[8] = {v0.x, v0.y, v0.z, v0.w, v1.x, v1.y, v1.z, v1.w};
    union { bf16 b[8]; uint4 q; } H, L;
    #pragma unroll
    for (int j = 0; j < 8; j++) {
        bf16 h = __float2bfloat16(vv[j]);
        H.b[j] = h;
        L.b[j] = __float2bfloat16(vv[j] - __bfloat162float(h));
    }
    *(uint4*)(g_Ah + (size_t)m * Dd + d0) = H.q;
    *(uint4*)(g_Al + (size_t)m * Dd + d0) = L.q;
}

// ===================================================================
// conv_w: Wx [d][g] fp32 -> transposed bf16 hi/lo [g][d].
// ===================================================================
__global__ void conv_w(const float* __restrict__ Wx) {
    size_t u = (size_t)blockIdx.x * blockDim.x + threadIdx.x;
    int g  = (int)(u & 4095);
    int d0 = (int)(u >> 12) << 3;
    union { bf16 b[8]; uint4 q; } H, L;
    #pragma unroll
    for (int j = 0; j < 8; j++) {
        float v = Wx[(size_t)(d0 + j) * Gg + g];
        bf16 h = __float2bfloat16(v);
        H.b[j] = h;
        L.b[j] = __float2bfloat16(v - __bfloat162float(h));
    }
    *(uint4*)(g_Bh + (size_t)g * Dd + d0) = H.q;
    *(uint4*)(g_Bl + (size_t)g * Dd + d0) = L.q;
}

// ===================================================================
// tc_gemm: xW = A @ B^T + bias via mma.sync (UNCHANGED, passing R12-R14).
// ===================================================================
typedef bf16 SmTile[128][40];

__global__ __launch_bounds__(256, 2) void tc_gemm(const float* __restrict__ bias) {
    extern __shared__ bf16 smraw[];
    SmTile* tiles = (SmTile*)smraw;

    const int tid = threadIdx.x;
    const int wid = tid >> 5;
    const int lid = tid & 31;
    const int grp = lid >> 2;
    const int tg  = lid & 3;
    const int wm  = wid >> 2;
    const int wn  = wid & 3;
    const int n0  = blockIdx.x * 128;
    const int m0  = blockIdx.y * 128;

    #define LOADTILES(buf, kt) do { \
        _Pragma("unroll") \
        for (int q = 0; q < 2; q++) { \
            int c  = tid * 2 + q; \
            int r  = c >> 2; \
            int kc = (c & 3) * 8; \
            size_t goff = (size_t)r * Dd + (kt) + kc; \
            cp16(&tiles[(buf)*4 + 0][r][kc], g_Ah + (size_t)m0 * Dd + goff); \
            cp16(&tiles[(buf)*4 + 1][r][kc], g_Al + (size_t)m0 * Dd + goff); \
            cp16(&tiles[(buf)*4 + 2][r][kc], g_Bh + (size_t)n0 * Dd + goff); \
            cp16(&tiles[(buf)*4 + 3][r][kc], g_Bl + (size_t)n0 * Dd + goff); \
        } \
    } while (0)

    float acc[4][4][4];
    #pragma unroll
    for (int mt = 0; mt < 4; mt++)
        #pragma unroll
        for (int nt = 0; nt < 4; nt++)
            #pragma unroll
            for (int e = 0; e < 4; e++) acc[mt][nt][e] = 0.0f;

    LOADTILES(0, 0);
    CP_COMMIT();

    int buf = 0;
    for (int kt = 0; kt < Dd; kt += 32) {
        if (kt + 32 < Dd) LOADTILES(buf ^ 1, kt + 32);
        CP_COMMIT();
        CP_WAIT1();
        __syncthreads();

        const SmTile& Ah_s = tiles[buf * 4 + 0];
        const SmTile& Al_s = tiles[buf * 4 + 1];
        const SmTile& Bh_s = tiles[buf * 4 + 2];
        const SmTile& Bl_s = tiles[buf * 4 + 3];

        #pragma unroll
        for (int ks = 0; ks < 32; ks += 16) {
            uint32_t af[4][4], bfr[4][2];
            const int k0 = ks + tg * 2;

            #pragma unroll
            for (int mt = 0; mt < 4; mt++) {
                int r = wm * 64 + mt * 16 + grp;
                af[mt][0] = *(const uint32_t*)&Ah_s[r][k0];
                af[mt][1] = *(const uint32_t*)&Ah_s[r + 8][k0];
                af[mt][2] = *(const uint32_t*)&Ah_s[r][k0 + 8];
                af[mt][3] = *(const uint32_t*)&Ah_s[r + 8][k0 + 8];
            }
            #pragma unroll
            for (int nt = 0; nt < 4; nt++) {
                int r = wn * 32 + nt * 8 + grp;
                bfr[nt][0] = *(const uint32_t*)&Bh_s[r][k0];
                bfr[nt][1] = *(const uint32_t*)&Bh_s[r][k0 + 8];
            }
            #pragma unroll
            for (int mt = 0; mt < 4; mt++)
                #pragma unroll
                for (int nt = 0; nt < 4; nt++)
                    MMA16816(acc[mt][nt], af[mt][0], af[mt][1], af[mt][2], af[mt][3],
                             bfr[nt][0], bfr[nt][1]);

            #pragma unroll
            for (int nt = 0; nt < 4; nt++) {
                int r = wn * 32 + nt * 8 + grp;
                bfr[nt][0] = *(const uint32_t*)&Bl_s[r][k0];
                bfr[nt][1] = *(const uint32_t*)&Bl_s[r][k0 + 8];
            }
            #pragma unroll
            for (int mt = 0; mt < 4; mt++)
                #pragma unroll
                for (int nt = 0; nt < 4; nt++)
                    MMA16816(acc[mt][nt], af[mt][0], af[mt][1], af[mt][2], af[mt][3],
                             bfr[nt][0], bfr[nt][1]);

            #pragma unroll
            for (int mt = 0; mt < 4; mt++) {
                int r = wm * 64 + mt * 16 + grp;
                af[mt][0] = *(const uint32_t*)&Al_s[r][k0];
                af[mt][1] = *(const uint32_t*)&Al_s[r + 8][k0];
                af[mt][2] = *(const uint32_t*)&Al_s[r][k0 + 8];
                af[mt][3] = *(const uint32_t*)&Al_s[r + 8][k0 + 8];
            }
            #pragma unroll
            for (int nt = 0; nt < 4; nt++) {
                int r = wn * 32 + nt * 8 + grp;
                bfr[nt][0] = *(const uint32_t*)&Bh_s[r][k0];
                bfr[nt][1] = *(const uint32_t*)&Bh_s[r][k0 + 8];
            }
            #pragma unroll
            for (int mt = 0; mt < 4; mt++)
                #pragma unroll
                for (int nt = 0; nt < 4; nt++)
                    MMA16816(acc[mt][nt], af[mt][0], af[mt][1], af[mt][2], af[mt][3],
                             bfr[nt][0], bfr[nt][1]);
        }
        __syncthreads();
        buf ^= 1;
    }

    #pragma unroll
    for (int mt = 0; mt < 4; mt++) {
        int mrow = m0 + wm * 64 + mt * 16 + grp;
        #pragma unroll
        for (int nt = 0; nt < 4; nt++) {
            int col = n0 + wn * 32 + nt * 8 + tg * 2;
            float2 bv = *(const float2*)(bias + col);
            float2 v0 = make_float2(acc[mt][nt][0] + bv.x, acc[mt][nt][1] + bv.y);
            float2 v1 = make_float2(acc[mt][nt][2] + bv.x, acc[mt][nt][3] + bv.y);
            *(float2*)(g_xw + (size_t)mrow * Gg + col) = v0;
            *(float2*)(g_xw + (size_t)(mrow + 8) * Gg + col) = v1;
        }
    }
    #undef LOADTILES
}

// ===================================================================
// Kernel 2: persistent LSTM recurrence — fine-grained flag dataflow.
// Changes vs passing R14:
//  * Per-CTA monotonic flags replace quarter counters. Chunk ch of
//    group g depends on exactly 2 producer CTAs (32g+2ch, +1); loaders
//    probe those 2 flags (relaxed polls + fence.acq_rel on success)
//    right before issuing the chunk. The step-start quarter spin and
//    its bar are GONE — handoff latency and producer skew overlap
//    with compute instead of serializing at a step barrier.
//  * WAR safety: a CTA writes h for step t only after its 16 probes
//    observed flag >= t from all 128 CTAs (union over its 4 groups)
//    and the CTA-wide sync; flag[c'] >= t implies c' finished READING
//    buffer (t-1)&1, which is the write target. Acyclic, deadlock-free.
//  * compute(ch) moved before the prefetch issue within each iter
//    (probe stall overlaps ready work); write target buf[(ch+3)&3]'s
//    readers (compute(ch-1)) completed before this iter's bar.
//  * fast tanh via __expf; out[] store moved after the flag publish.
// smem: Wh 132096 + stages 98304 = 230400 B (unchanged).
// ===================================================================
#define WH_STRIDE 1032
#define HROW 24           // bf16 per staged h row (16 used + 8 pad); 48 B
#define GSTG 24576        // per-group stage region: 4 bufs x 6144 B

__global__ __launch_bounds__(512, 1) void lstm_persist(const float* __restrict__ Wh,
                                                       float* __restrict__ out) {
    extern __shared__ char smc[];
    bf16*  Whh = (bf16*)smc;                          // [32][1032]
    bf16*  Whl = Whh + 32 * WH_STRIDE;                // [32][1032]
    char*  hSb = smc + 132096;                        // 4 groups x 4 bufs x 6144 B

    const int tid = threadIdx.x;
    const int j0  = blockIdx.x * 8;
    const int g   = tid >> 7;               // K-split group 0..3
    const int tl  = tid & 127;
    const int wg  = tl >> 5;                // warp in group 0..3 -> m-tile
    const int lid = tid & 31;
    const int grp = lid >> 2;               // 0..7
    const int tg  = lid & 3;                // 0..3
    const int n   = tid >> 3;               // gate-stage row 0..63
    const int jj  = tid & 7;                // gate-stage col 0..7

    // ---- convert Wh slice -> smem bf16 hi/lo [c][k], c = gate*8+jj ----
    {
        int c  = tid & 31;
        int gate = c >> 3, cj = c & 7;
        const float* wp = Wh + (size_t)gate * Hh + j0 + cj;
        for (int k = tid >> 5; k < Hh; k += 16) {
            float w = wp[(size_t)k * Gg];
            bf16 wh = __float2bfloat16(w);
            Whh[c * WH_STRIDE + k] = wh;
            Whl[c * WH_STRIDE + k] = __float2bfloat16(w - __bfloat162float(wh));
        }
    }
    __syncthreads();

    float c_reg = 0.0f;
    const int kbase = g * 256;
    char*  hg     = hSb + g * GSTG;          // 4 stage bufs, 6144 B each
    float* mypart = (float*)hg;              // partials alias bufs 0-1 (8448 B)

    const int ar = wg * 16 + grp;            // A-frag row within [64]

    // probe the 2 producers of chunk ch (flags >= t) — relaxed polls,
    // one gpu-scope acquire fence on success (pairs with producer release)
    #define PROBE2(ch, tt) do { \
        const int* fp = g_flagc + (g << 5) + ((ch) << 1); \
        int _v0, _v1; \
        while (true) { \
            asm volatile("ld.relaxed.gpu.global.b32 %0, [%1];" : "=r"(_v0) : "l"(fp)     : "memory"); \
            asm volatile("ld.relaxed.gpu.global.b32 %0, [%1];" : "=r"(_v1) : "l"(fp + 1) : "memory"); \
            if (_v0 >= (tt) && _v1 >= (tt)) break; \
        } \
        asm volatile("fence.acq_rel.gpu;" ::: "memory"); \
    } while (0)

    for (int t = 0; t < Ts; t++) {
        const bf16* hbh = g_hbh[t & 1];
        const bf16* hbl = g_hbl[t & 1];
        bf16* hoh = g_hbh[(t + 1) & 1];
        bf16* hol = g_hbl[(t + 1) & 1];

        // prefetch xW addends (DRAM latency overlaps the chunk pipeline)
        const float* xwp = g_xw + ((size_t)t * Nb + n) * Gg + j0 + jj;
        float xi = xwp[0], xf = xwp[Hh], xo = xwp[2 * Hh], xg = xwp[3 * Hh];

        float acc[4][4];
        #pragma unroll
        for (int nt = 0; nt < 4; nt++)
            #pragma unroll
            for (int e = 0; e < 4; e++) acc[nt][e] = 0.0f;

        // stage loader: 2 jobs/thread/chunk (hi + lo halves).
        #define LOADCHUNK(dst, ch) do { \
            _Pragma("unroll") \
            for (int q = 0; q < 2; q++) { \
                int j2 = tl + q * 128; \
                int half = j2 >> 7; \
                int r = (j2 & 127) >> 1; \
                int seg = j2 & 1; \
                const bf16* srcb = (half ? hbl : hbh) + (size_t)r * Hh + kbase + (ch) * 16 + seg * 8; \
                cp16((dst) + half * 3072 + r * 48 + seg * 16, srcb); \
            } \
        } while (0)

        // prologue: probe+stage chunks 0,1,2 into bufs 0,1,2
        PROBE2(0, t); LOADCHUNK(hg + 0 * 6144, 0); CP_COMMIT();
        PROBE2(1, t); LOADCHUNK(hg + 1 * 6144, 1); CP_COMMIT();
        PROBE2(2, t); LOADCHUNK(hg + 2 * 6144, 2); CP_COMMIT();

        #pragma unroll 1
        for (int ch = 0; ch < 16; ch++) {
            CP_WAIT2();                                                 // chunk ch landed
            asm volatile("bar.sync %0, 128;" :: "r"(g + 1) : "memory"); // data visible;
                                                                        // compute(ch-1) done

            const bf16* Ah = (const bf16*)(hg + (ch & 3) * 6144);       // [64][24]
            const bf16* Al = Ah + 1536;
            const int kk = kbase + ch * 16 + tg * 2;                    // B k index

            uint32_t ah0 = *(const uint32_t*)&Ah[ar * HROW + tg * 2];
            uint32_t ah1 = *(const uint32_t*)&Ah[(ar + 8) * HROW + tg * 2];
            uint32_t ah2 = *(const uint32_t*)&Ah[ar * HROW + tg * 2 + 8];
            uint32_t ah3 = *(const uint32_t*)&Ah[(ar + 8) * HROW + tg * 2 + 8];
            uint32_t al0 = *(const uint32_t*)&Al[ar * HROW + tg * 2];
            uint32_t al1 = *(const uint32_t*)&Al[(ar + 8) * HROW + tg * 2];
            uint32_t al2 = *(const uint32_t*)&Al[ar * HROW + tg * 2 + 8];
            uint32_t al3 = *(const uint32_t*)&Al[(ar + 8) * HROW + tg * 2 + 8];

            #pragma unroll
            for (int nt = 0; nt < 4; nt++) {
                int br = nt * 8 + grp;
                uint32_t bh0 = *(const uint32_t*)&Whh[br * WH_STRIDE + kk];
                uint32_t bh1 = *(const uint32_t*)&Whh[br * WH_STRIDE + kk + 8];
                uint32_t bl0 = *(const uint32_t*)&Whl[br * WH_STRIDE + kk];
                uint32_t bl1 = *(const uint32_t*)&Whl[br * WH_STRIDE + kk + 8];
                MMA16816(acc[nt], ah0, ah1, ah2, ah3, bh0, bh1);
                MMA16816(acc[nt], ah0, ah1, ah2, ah3, bl0, bl1);
                MMA16816(acc[nt], al0, al1, al2, al3, bh0, bh1);
            }

            // prefetch chunk ch+3 (probe its 2 producers, then issue)
            if (ch < 13) {
                PROBE2(ch + 3, t);
                LOADCHUNK(hg + ((ch + 3) & 3) * 6144, ch + 3);
            }
            CP_COMMIT();
        }
        #undef LOADCHUNK

        // write K-split partials into this group's stage bufs 0-1 ([64][33]).
        // Safe: bars through iter 15 covered compute(<=14); ch15 read buf3.
        #pragma unroll
        for (int nt = 0; nt < 4; nt++) {
            int col = nt * 8 + tg * 2;
            float* p0 = mypart + ar * 33 + col;
            p0[0] = acc[nt][0]; p0[1] = acc[nt][1];
            float* p1 = mypart + (ar + 8) * 33 + col;
            p1[0] = acc[nt][2]; p1[1] = acc[nt][3];
        }
        __syncthreads();   // all groups' partials visible

        // gates: reduce 4 partials + xW, update c (register), emit h
        float Ai = xi, Af = xf, Ao = xo, Ag = xg;
        #pragma unroll
        for (int gr = 0; gr < 4; gr++) {
            const float* p = (const float*)(hSb + gr * GSTG) + n * 33;
            Ai += p[jj]; Af += p[8 + jj]; Ao += p[16 + jj]; Ag += p[24 + jj];
        }
        float ig = __fdividef(1.0f, 1.0f + __expf(-Ai));
        float fg = __fdividef(1.0f, 1.0f + __expf(-Af));
        float og = __fdividef(1.0f, 1.0f + __expf(-Ao));
        float gg = __fdividef(2.0f, 1.0f + __expf(-2.0f * Ag)) - 1.0f;
        c_reg = fg * c_reg + ig * gg;
        float th = __fdividef(2.0f, 1.0f + __expf(-2.0f * c_reg)) - 1.0f;
        float hv = og * th;

        bf16 hh = __float2bfloat16(hv);
        hoh[n * Hh + j0 + jj] = hh;
        hol[n * Hh + j0 + jj] = __float2bfloat16(hv - __bfloat162float(hh));

        // publish ASAP: h columns for step t+1 are ready (release store)
        __syncthreads();                      // all threads' h writes done
        if (tid == 0) {
            __threadfence();
            asm volatile("st.relaxed.gpu.global.b32 [%0], %1;"
                         :: "l"(g_flagc + blockIdx.x), "r"(t + 1) : "memory");
        }

        // out[] store off the critical chain (nobody else reads it)
        out[((size_t)n * Ts + t) * Hh + j0 + jj] = hv;
    }
    #undef PROBE2
}

// ===================================================================
// Host launch
// ===================================================================
extern "C" void kernel_launch(void* const* d_in, const int* in_sizes, int n_in,
                              void* d_out, int out_size) {
    const float* x  = (const float*)d_in[0];   // (64, 512, 1024)
    const float* h0 = (const float*)d_in[1];   // (64, 1024)
    const float* Wx = (const float*)d_in[2];   // (1024, 4096)
    const float* Wh = (const float*)d_in[3];   // (1024, 4096)
    const float* b  = (const float*)d_in[4];   // (4096)
    float* out = (float*)d_out;                // (64, 512, 1024)

    cudaFuncSetAttribute(lstm_persist, cudaFuncAttributeMaxDynamicSharedMemorySize, 230400);
    cudaFuncSetAttribute(tc_gemm, cudaFuncAttributeMaxDynamicSharedMemorySize, 81920);

    prep<<<64, 256>>>(h0);
    conv_x<<<16384, 256>>>(x);
    conv_w<<<2048, 256>>>(Wx);

    dim3 gg(Gg / 128, (Nb * Ts) / 128);        // (32, 256) — N fastest for A L2 reuse
    tc_gemm<<<gg, 256, 81920>>>(b);

    lstm_persist<<<128, 512, 230400>>>(Wh, out);
}

// round 16
// speedup vs baseline: 2.4694x; 2.4694x over previous
#include <cuda_runtime.h>
#include <cuda_bf16.h>
#include <cstddef>
#include <cstdint>

#define Nb 64
#define Ts 512
#define Dd 1024
#define Hh 1024
#define Gg 4096   // 4*Hh

typedef unsigned long long u64;
typedef __nv_bfloat16 bf16;

// Scratch (static device arrays; no allocations).
__device__ float g_xw[(size_t)Nb * Ts * Gg];     // (t, n, 4H)
__device__ int   g_barq[Ts][4];                  // per-step, per-quarter barrier counters

// h state for the recurrence, bf16 hi/lo split, [n][k] layout, double-buffered.
__device__ __align__(16) bf16 g_hbh[2][Nb * Hh];
__device__ __align__(16) bf16 g_hbl[2][Nb * Hh];

// bf16-split operands for the tensor-core input GEMM.
__device__ __align__(16) bf16 g_Ah[(size_t)Nb * Ts * Dd];  // A hi [m][d], m=t*64+n
__device__ __align__(16) bf16 g_Al[(size_t)Nb * Ts * Dd];  // A lo
__device__ __align__(16) bf16 g_Bh[(size_t)Gg * Dd];       // Wx^T hi [g][d]
__device__ __align__(16) bf16 g_Bl[(size_t)Gg * Dd];       // Wx^T lo

__device__ __forceinline__ void cp16(void* smem, const void* g) {
    unsigned saddr = (unsigned)__cvta_generic_to_shared(smem);
    asm volatile("cp.async.cg.shared.global [%0], [%1], 16;" :: "r"(saddr), "l"(g));
}
#define CP_COMMIT() asm volatile("cp.async.commit_group;")
#define CP_WAIT1()  asm volatile("cp.async.wait_group 1;")
#define CP_WAIT2()  asm volatile("cp.async.wait_group 2;")

__device__ __forceinline__ uint32_t smem_u32(const void* p) {
    uint32_t a;
    asm("{ .reg .u64 t; cvta.to.shared.u64 t, %1; cvt.u32.u64 %0, t; }" : "=r"(a) : "l"(p));
    return a;
}

// mma.sync m16n8k16 row.col f32.bf16.bf16.f32 — baseline PTX (works on compute_103).
#define MMA16816(c, a0, a1, a2, a3, b0, b1) \
    asm volatile("mma.sync.aligned.m16n8k16.row.col.f32.bf16.bf16.f32 " \
                 "{%0,%1,%2,%3}, {%4,%5,%6,%7}, {%8,%9}, {%0,%1,%2,%3};" \
                 : "+f"((c)[0]), "+f"((c)[1]), "+f"((c)[2]), "+f"((c)[3]) \
                 : "r"(a0), "r"(a1), "r"(a2), "r"(a3), "r"(b0), "r"(b1))

// ldmatrix x4 — baseline PTX since sm_75.
#define LDSM4(r0, r1, r2, r3, addr) \
    asm volatile("ldmatrix.sync.aligned.m8n8.x4.shared.b16 {%0,%1,%2,%3}, [%4];" \
                 : "=r"(r0), "=r"(r1), "=r"(r2), "=r"(r3) : "r"(addr))

// ===================================================================
// prep: zero per-step quarter-barrier counters; convert h0 -> bf16 hi/lo
// ===================================================================
__global__ void prep(const float* __restrict__ h0) {
    int tid = blockIdx.x * blockDim.x + threadIdx.x;
    int nt  = gridDim.x * blockDim.x;
    if (tid < Ts * 4) ((int*)g_barq)[tid] = 0;
    for (int i = tid; i < Nb * Hh; i += nt) {
        float v = h0[i];
        bf16 hh = __float2bfloat16(v);
        g_hbh[0][i] = hh;
        g_hbl[0][i] = __float2bfloat16(v - __bfloat162float(hh));
    }
}

// ===================================================================
// conv_x: x (N,T,D) fp32 -> bf16 hi/lo rows m = t*64+n.
// ===================================================================
__global__ void conv_x(const float* __restrict__ x) {
    size_t u = (size_t)blockIdx.x * blockDim.x + threadIdx.x;
    int m  = (int)(u >> 7);
    int d0 = (int)(u & 127) << 3;
    int t = m >> 6, n = m & 63;
    const float* src = x + ((size_t)n * Ts + t) * Dd + d0;
    float4 v0 = *(const float4*)src;
    float4 v1 = *(const float4*)(src + 4);
    float vv[8] = {v0.x, v0.y, v0.z, v0.w, v1.x, v1.y, v1.z, v1.w};
    union { bf16 b[8]; uint4 q; } H, L;
    #pragma unroll
    for (int j = 0; j < 8; j++) {
        bf16 h = __float2bfloat16(vv[j]);
        H.b[j] = h;
        L.b[j] = __float2bfloat16(vv[j] - __bfloat162float(h));
    }
    *(uint4*)(g_Ah + (size_t)m * Dd + d0) = H.q;
    *(uint4*)(g_Al + (size_t)m * Dd + d0) = L.q;
}

// ===================================================================
// conv_w: Wx [d][g] fp32 -> transposed bf16 hi/lo [g][d].
// ===================================================================
__global__ void conv_w(const float* __restrict__ Wx) {
    size_t u = (size_t)blockIdx.x * blockDim.x + threadIdx.x;
    int g  = (int)(u & 4095);
    int d0 = (int)(u >> 12) << 3;
    union { bf16 b[8]; uint4 q; } H, L;
    #pragma unroll
    for (int j = 0; j < 8; j++) {
        float v = Wx[(size_t)(d0 + j) * Gg + g];
        bf16 h = __float2bfloat16(v);
        H.b[j] = h;
        L.b[j] = __float2bfloat16(v - __bfloat162float(h));
    }
    *(uint4*)(g_Bh + (size_t)g * Dd + d0) = H.q;
    *(uint4*)(g_Bl + (size_t)g * Dd + d0) = L.q;
}

// ===================================================================
// tc_gemm: xW = A @ B^T + bias via mma.sync. Same tiling as passing
// R12-R14 (BM=BN=128, BK=32, 8 warps, warp tile 64x32), but fragment
// loads via ldmatrix.x4 (12 LDSM per warp-k16 instead of ~56 LDS.32).
// Frag mapping verified against the R12 scalar loads:
//   A x4: lanes 0-7/8-15/16-23/24-31 -> a0/a1/a2/a3 of m16k16.
//   B x4: covers two n8 tiles -> (b0,b1) of nt and nt+1.
// [128][40] rows (20-word stride) put the 8 LDSM rows on disjoint banks.
// bh frags stay live for term 3; al reuses ah's registers.
// ===================================================================
typedef bf16 SmTile[128][40];    // 10,240 B per tile

__global__ __launch_bounds__(256, 2) void tc_gemm(const float* __restrict__ bias) {
    extern __shared__ bf16 smraw[];
    SmTile* tiles = (SmTile*)smraw;

    const int tid = threadIdx.x;
    const int wid = tid >> 5;
    const int lid = tid & 31;
    const int wm  = wid >> 2;
    const int wn  = wid & 3;
    const int n0  = blockIdx.x * 128;
    const int m0  = blockIdx.y * 128;

    // per-thread ldmatrix lane offsets (bytes from tile base)
    const uint32_t sb0  = smem_u32(smraw);
    const uint32_t offA = ((wm * 64 + (lid & 15)) * 40 + ((lid >> 4) << 3)) * 2;
    const uint32_t offB = ((wn * 32 + (lid & 7) + ((lid >> 4) << 3)) * 40
                           + (((lid >> 3) & 1) << 3)) * 2;

    #define LOADTILES(buf, kt) do { \
        _Pragma("unroll") \
        for (int q = 0; q < 2; q++) { \
            int c  = tid * 2 + q; \
            int r  = c >> 2; \
            int kc = (c & 3) * 8; \
            size_t goff = (size_t)r * Dd + (kt) + kc; \
            cp16(&tiles[(buf)*4 + 0][r][kc], g_Ah + (size_t)m0 * Dd + goff); \
            cp16(&tiles[(buf)*4 + 1][r][kc], g_Al + (size_t)m0 * Dd + goff); \
            cp16(&tiles[(buf)*4 + 2][r][kc], g_Bh + (size_t)n0 * Dd + goff); \
            cp16(&tiles[(buf)*4 + 3][r][kc], g_Bl + (size_t)n0 * Dd + goff); \
        } \
    } while (0)

    float acc[4][4][4];
    #pragma unroll
    for (int mt = 0; mt < 4; mt++)
        #pragma unroll
        for (int nt = 0; nt < 4; nt++)
            #pragma unroll
            for (int e = 0; e < 4; e++) acc[mt][nt][e] = 0.0f;

    LOADTILES(0, 0);
    CP_COMMIT();

    int buf = 0;
    for (int kt = 0; kt < Dd; kt += 32) {
        if (kt + 32 < Dd) LOADTILES(buf ^ 1, kt + 32);
        CP_COMMIT();
        CP_WAIT1();
        __syncthreads();

        const uint32_t baseAh = sb0 + (buf * 4 + 0) * 10240 + offA;
        const uint32_t baseAl = sb0 + (buf * 4 + 1) * 10240 + offA;
        const uint32_t baseBh = sb0 + (buf * 4 + 2) * 10240 + offB;
        const uint32_t baseBl = sb0 + (buf * 4 + 3) * 10240 + offB;

        #pragma unroll
        for (int ks = 0; ks < 32; ks += 16) {
            uint32_t a[4][4], bh[4][2], bl[4][2];

            #pragma unroll
            for (int mt = 0; mt < 4; mt++)
                LDSM4(a[mt][0], a[mt][1], a[mt][2], a[mt][3],
                      baseAh + mt * 1280 + ks * 2);
            #pragma unroll
            for (int p = 0; p < 2; p++) {
                uint32_t t0, t1, t2, t3;
                LDSM4(t0, t1, t2, t3, baseBh + p * 1280 + ks * 2);
                bh[2*p][0] = t0; bh[2*p][1] = t1;
                bh[2*p+1][0] = t2; bh[2*p+1][1] = t3;
                LDSM4(t0, t1, t2, t3, baseBl + p * 1280 + ks * 2);
                bl[2*p][0] = t0; bl[2*p][1] = t1;
                bl[2*p+1][0] = t2; bl[2*p+1][1] = t3;
            }

            // term 1: ah * bh
            #pragma unroll
            for (int mt = 0; mt < 4; mt++)
                #pragma unroll
                for (int nt = 0; nt < 4; nt++)
                    MMA16816(acc[mt][nt], a[mt][0], a[mt][1], a[mt][2], a[mt][3],
                             bh[nt][0], bh[nt][1]);
            // term 2: ah * bl
            #pragma unroll
            for (int mt = 0; mt < 4; mt++)
                #pragma unroll
                for (int nt = 0; nt < 4; nt++)
                    MMA16816(acc[mt][nt], a[mt][0], a[mt][1], a[mt][2], a[mt][3],
                             bl[nt][0], bl[nt][1]);
            // term 3: al * bh (al reuses a's registers)
            #pragma unroll
            for (int mt = 0; mt < 4; mt++)
                LDSM4(a[mt][0], a[mt][1], a[mt][2], a[mt][3],
                      baseAl + mt * 1280 + ks * 2);
            #pragma unroll
            for (int mt = 0; mt < 4; mt++)
                #pragma unroll
                for (int nt = 0; nt < 4; nt++)
                    MMA16816(acc[mt][nt], a[mt][0], a[mt][1], a[mt][2], a[mt][3],
                             bh[nt][0], bh[nt][1]);
        }
        __syncthreads();
        buf ^= 1;
    }

    const int grp = lid >> 2;
    const int tg  = lid & 3;
    #pragma unroll
    for (int mt = 0; mt < 4; mt++) {
        int mrow = m0 + wm * 64 + mt * 16 + grp;
        #pragma unroll
        for (int nt = 0; nt < 4; nt++) {
            int col = n0 + wn * 32 + nt * 8 + tg * 2;
            float2 bv = *(const float2*)(bias + col);
            float2 v0 = make_float2(acc[mt][nt][0] + bv.x, acc[mt][nt][1] + bv.y);
            float2 v1 = make_float2(acc[mt][nt][2] + bv.x, acc[mt][nt][3] + bv.y);
            *(float2*)(g_xw + (size_t)mrow * Gg + col) = v0;
            *(float2*)(g_xw + (size_t)(mrow + 8) * Gg + col) = v1;
        }
    }
    #undef LOADTILES
}

// ===================================================================
// Kernel 2: persistent LSTM recurrence — EXACT R14 skeleton (passing,
// 8588us): quarter counters, 4 stage bufs, wait_group 2, 1 bar/chunk,
// partials aliased into stage bufs 0-1. Only validated deltas applied:
// fast gates via __expf (R15-verified numerics) and out[] stored after
// the publish.
// ===================================================================
#define WH_STRIDE 1032
#define HROW 24           // bf16 per staged h row (16 used + 8 pad); 48 B
#define GSTG 24576        // per-group stage region: 4 bufs x 6144 B

__global__ __launch_bounds__(512, 1) void lstm_persist(const float* __restrict__ Wh,
                                                       float* __restrict__ out) {
    extern __shared__ char smc[];
    bf16*  Whh = (bf16*)smc;                          // [32][1032]
    bf16*  Whl = Whh + 32 * WH_STRIDE;                // [32][1032]
    char*  hSb = smc + 132096;                        // 4 groups x 4 bufs x 6144 B

    const int tid = threadIdx.x;
    const int j0  = blockIdx.x * 8;
    const int quarter = blockIdx.x >> 5;
    const int g   = tid >> 7;               // K-split group 0..3
    const int tl  = tid & 127;
    const int wg  = tl >> 5;                // warp in group 0..3 -> m-tile
    const int lid = tid & 31;
    const int grp = lid >> 2;               // 0..7
    const int tg  = lid & 3;                // 0..3
    const int n   = tid >> 3;               // gate-stage row 0..63
    const int jj  = tid & 7;                // gate-stage col 0..7

    // ---- convert Wh slice -> smem bf16 hi/lo [c][k], c = gate*8+jj ----
    {
        int c  = tid & 31;
        int gate = c >> 3, cj = c & 7;
        const float* wp = Wh + (size_t)gate * Hh + j0 + cj;
        for (int k = tid >> 5; k < Hh; k += 16) {
            float w = wp[(size_t)k * Gg];
            bf16 wh = __float2bfloat16(w);
            Whh[c * WH_STRIDE + k] = wh;
            Whl[c * WH_STRIDE + k] = __float2bfloat16(w - __bfloat162float(wh));
        }
    }
    __syncthreads();

    float c_reg = 0.0f;
    const int kbase = g * 256;
    char*  hg     = hSb + g * GSTG;          // 4 stage bufs, 6144 B each
    float* mypart = (float*)hg;              // partials alias bufs 0-1 (8448 B)

    const int ar = wg * 16 + grp;            // A-frag row within [64]

    for (int t = 0; t < Ts; t++) {
        const bf16* hbh = g_hbh[t & 1];
        const bf16* hbl = g_hbl[t & 1];
        bf16* hoh = g_hbh[(t + 1) & 1];
        bf16* hol = g_hbl[(t + 1) & 1];

        // prefetch xW addends (DRAM latency overlaps the spin below)
        const float* xwp = g_xw + ((size_t)t * Nb + n) * Gg + j0 + jj;
        float xi = xwp[0], xf = xwp[Hh], xo = xwp[2 * Hh], xg = xwp[3 * Hh];

        // per-group input-ready wait: quarter g published step-t input
        if (t > 0) {
            if (tl == 0) {
                int v;
                do {
                    asm volatile("ld.acquire.gpu.global.b32 %0, [%1];"
                                 : "=r"(v) : "l"(&g_barq[t - 1][g]) : "memory");
                } while (v < 32);
            }
            asm volatile("bar.sync %0, 128;" :: "r"(g + 1) : "memory");
        }

        float acc[4][4];
        #pragma unroll
        for (int nt = 0; nt < 4; nt++)
            #pragma unroll
            for (int e = 0; e < 4; e++) acc[nt][e] = 0.0f;

        // stage loader: 2 jobs/thread/chunk (hi + lo halves).
        #define LOADCHUNK(dst, ch) do { \
            _Pragma("unroll") \
            for (int q = 0; q < 2; q++) { \
                int j2 = tl + q * 128; \
                int half = j2 >> 7; \
                int r = (j2 & 127) >> 1; \
                int seg = j2 & 1; \
                const bf16* srcb = (half ? hbl : hbh) + (size_t)r * Hh + kbase + (ch) * 16 + seg * 8; \
                cp16((dst) + half * 3072 + r * 48 + seg * 16, srcb); \
            } \
        } while (0)

        // prologue: chunks 0,1,2 into bufs 0,1,2 (3 committed groups)
        LOADCHUNK(hg + 0 * 6144, 0); CP_COMMIT();
        LOADCHUNK(hg + 1 * 6144, 1); CP_COMMIT();
        LOADCHUNK(hg + 2 * 6144, 2); CP_COMMIT();

        #pragma unroll 1
        for (int ch = 0; ch < 16; ch++) {
            CP_WAIT2();                                               // chunk ch landed
            asm volatile("bar.sync %0, 128;" :: "r"(g + 1) : "memory"); // readers of
                                                                        // buf[(ch-1)&3] done
            if (ch < 13) LOADCHUNK(hg + ((ch + 3) & 3) * 6144, ch + 3);
            CP_COMMIT();

            const bf16* Ah = (const bf16*)(hg + (ch & 3) * 6144);     // [64][24]
            const bf16* Al = Ah + 1536;
            const int kk = kbase + ch * 16 + tg * 2;                  // B k index

            uint32_t ah0 = *(const uint32_t*)&Ah[ar * HROW + tg * 2];
            uint32_t ah1 = *(const uint32_t*)&Ah[(ar + 8) * HROW + tg * 2];
            uint32_t ah2 = *(const uint32_t*)&Ah[ar * HROW + tg * 2 + 8];
            uint32_t ah3 = *(const uint32_t*)&Ah[(ar + 8) * HROW + tg * 2 + 8];
            uint32_t al0 = *(const uint32_t*)&Al[ar * HROW + tg * 2];
            uint32_t al1 = *(const uint32_t*)&Al[(ar + 8) * HROW + tg * 2];
            uint32_t al2 = *(const uint32_t*)&Al[ar * HROW + tg * 2 + 8];
            uint32_t al3 = *(const uint32_t*)&Al[(ar + 8) * HROW + tg * 2 + 8];

            #pragma unroll
            for (int nt = 0; nt < 4; nt++) {
                int br = nt * 8 + grp;
                uint32_t bh0 = *(const uint32_t*)&Whh[br * WH_STRIDE + kk];
                uint32_t bh1 = *(const uint32_t*)&Whh[br * WH_STRIDE + kk + 8];
                uint32_t bl0 = *(const uint32_t*)&Whl[br * WH_STRIDE + kk];
                uint32_t bl1 = *(const uint32_t*)&Whl[br * WH_STRIDE + kk + 8];
                MMA16816(acc[nt], ah0, ah1, ah2, ah3, bh0, bh1);
                MMA16816(acc[nt], ah0, ah1, ah2, ah3, bl0, bl1);
                MMA16816(acc[nt], al0, al1, al2, al3, bh0, bh1);
            }
        }
        #undef LOADCHUNK

        // write K-split partials into this group's stage bufs 0-1 ([64][33]).
        #pragma unroll
        for (int nt = 0; nt < 4; nt++) {
            int col = nt * 8 + tg * 2;
            float* p0 = mypart + ar * 33 + col;
            p0[0] = acc[nt][0]; p0[1] = acc[nt][1];
            float* p1 = mypart + (ar + 8) * 33 + col;
            p1[0] = acc[nt][2]; p1[1] = acc[nt][3];
        }
        __syncthreads();   // all groups' partials visible; orders spins before h writes

        // gates: reduce 4 partials + xW, update c (register), emit h
        float Ai = xi, Af = xf, Ao = xo, Ag = xg;
        #pragma unroll
        for (int gr = 0; gr < 4; gr++) {
            const float* p = (const float*)(hSb + gr * GSTG) + n * 33;
            Ai += p[jj]; Af += p[8 + jj]; Ao += p[16 + jj]; Ag += p[24 + jj];
        }
        float ig = __fdividef(1.0f, 1.0f + __expf(-Ai));
        float fg = __fdividef(1.0f, 1.0f + __expf(-Af));
        float og = __fdividef(1.0f, 1.0f + __expf(-Ao));
        float gg = __fdividef(2.0f, 1.0f + __expf(-2.0f * Ag)) - 1.0f;
        c_reg = fg * c_reg + ig * gg;
        float th = __fdividef(2.0f, 1.0f + __expf(-2.0f * c_reg)) - 1.0f;
        float hv = og * th;

        bf16 hh = __float2bfloat16(hv);
        hoh[n * Hh + j0 + jj] = hh;
        hol[n * Hh + j0 + jj] = __float2bfloat16(hv - __bfloat162float(hh));

        // publish: this CTA's h columns for step t+1 are ready
        __syncthreads();                      // all 512 threads' h writes done
        if (tid == 0) {
            __threadfence();
            atomicAdd(&g_barq[t][quarter], 1);
        }

        // out[] store off the critical chain (nobody else reads it)
        out[((size_t)n * Ts + t) * Hh + j0 + jj] = hv;
    }
}

// ===================================================================
// Host launch
// ===================================================================
extern "C" void kernel_launch(void* const* d_in, const int* in_sizes, int n_in,
                              void* d_out, int out_size) {
    const float* x  = (const float*)d_in[0];   // (64, 512, 1024)
    const float* h0 = (const float*)d_in[1];   // (64, 1024)
    const float* Wx = (const float*)d_in[2];   // (1024, 4096)
    const float* Wh = (const float*)d_in[3];   // (1024, 4096)
    const float* b  = (const float*)d_in[4];   // (4096)
    float* out = (float*)d_out;                // (64, 512, 1024)

    cudaFuncSetAttribute(lstm_persist, cudaFuncAttributeMaxDynamicSharedMemorySize, 230400);
    cudaFuncSetAttribute(tc_gemm, cudaFuncAttributeMaxDynamicSharedMemorySize, 81920);

    prep<<<64, 256>>>(h0);
    conv_x<<<16384, 256>>>(x);
    conv_w<<<2048, 256>>>(Wx);

    dim3 gg(Gg / 128, (Nb * Ts) / 128);        // (32, 256) — N fastest for A L2 reuse
    tc_gemm<<<gg, 256, 81920>>>(b);

    lstm_persist<<<128, 512, 230400>>>(Wh, out);
}

// round 17
// speedup vs baseline: 2.5256x; 1.0227x over previous
#include <cuda_runtime.h>
#include <cuda_bf16.h>
#include <cstddef>
#include <cstdint>

#define Nb 64
#define Ts 512
#define Dd 1024
#define Hh 1024
#define Gg 4096   // 4*Hh

typedef unsigned long long u64;
typedef __nv_bfloat16 bf16;

// Scratch (static device arrays; no allocations).
__device__ float g_xw[(size_t)Nb * Ts * Gg];     // (t, n, 4H)
__device__ int   g_barq[Ts][4];                  // per-step, per-quarter barrier counters

// h state for the recurrence, bf16 hi/lo split, [n][k] layout, double-buffered.
__device__ __align__(16) bf16 g_hbh[2][Nb * Hh];
__device__ __align__(16) bf16 g_hbl[2][Nb * Hh];

// bf16-split operands for the tensor-core input GEMM.
__device__ __align__(16) bf16 g_Ah[(size_t)Nb * Ts * Dd];  // A hi [m][d], m=t*64+n
__device__ __align__(16) bf16 g_Al[(size_t)Nb * Ts * Dd];  // A lo
__device__ __align__(16) bf16 g_Bh[(size_t)Gg * Dd];       // Wx^T hi [g][d]
__device__ __align__(16) bf16 g_Bl[(size_t)Gg * Dd];       // Wx^T lo

__device__ __forceinline__ void cp16(void* smem, const void* g) {
    unsigned saddr = (unsigned)__cvta_generic_to_shared(smem);
    asm volatile("cp.async.cg.shared.global [%0], [%1], 16;" :: "r"(saddr), "l"(g));
}
#define CP_COMMIT() asm volatile("cp.async.commit_group;")
#define CP_WAIT1()  asm volatile("cp.async.wait_group 1;")

__device__ __forceinline__ uint32_t smem_u32(const void* p) {
    uint32_t a;
    asm("{ .reg .u64 t; cvta.to.shared.u64 t, %1; cvt.u32.u64 %0, t; }" : "=r"(a) : "l"(p));
    return a;
}

// mma.sync m16n8k16 row.col f32.bf16.bf16.f32 — baseline PTX (works on compute_103).
#define MMA16816(c, a0, a1, a2, a3, b0, b1) \
    asm volatile("mma.sync.aligned.m16n8k16.row.col.f32.bf16.bf16.f32 " \
                 "{%0,%1,%2,%3}, {%4,%5,%6,%7}, {%8,%9}, {%0,%1,%2,%3};" \
                 : "+f"((c)[0]), "+f"((c)[1]), "+f"((c)[2]), "+f"((c)[3]) \
                 : "r"(a0), "r"(a1), "r"(a2), "r"(a3), "r"(b0), "r"(b1))

// ldmatrix x4 — baseline PTX since sm_75.
#define LDSM4(r0, r1, r2, r3, addr) \
    asm volatile("ldmatrix.sync.aligned.m8n8.x4.shared.b16 {%0,%1,%2,%3}, [%4];" \
                 : "=r"(r0), "=r"(r1), "=r"(r2), "=r"(r3) : "r"(addr))

// ===================================================================
// prep: zero per-step quarter-barrier counters; convert h0 -> bf16 hi/lo
// ===================================================================
__global__ void prep(const float* __restrict__ h0) {
    int tid = blockIdx.x * blockDim.x + threadIdx.x;
    int nt  = gridDim.x * blockDim.x;
    if (tid < Ts * 4) ((int*)g_barq)[tid] = 0;
    for (int i = tid; i < Nb * Hh; i += nt) {
        float v = h0[i];
        bf16 hh = __float2bfloat16(v);
        g_hbh[0][i] = hh;
        g_hbl[0][i] = __float2bfloat16(v - __bfloat162float(hh));
    }
}

// ===================================================================
// conv_x: x (N,T,D) fp32 -> bf16 hi/lo rows m = t*64+n.
// ===================================================================
__global__ void conv_x(const float* __restrict__ x) {
    size_t u = (size_t)blockIdx.x * blockDim.x + threadIdx.x;
    int m  = (int)(u >> 7);
    int d0 = (int)(u & 127) << 3;
    int t = m >> 6, n = m & 63;
    const float* src = x + ((size_t)n * Ts + t) * Dd + d0;
    float4 v0 = *(const float4*)src;
    float4 v1 = *(const float4*)(src + 4);
    float vv[8] = {v0.x, v0.y, v0.z, v0.w, v1.x, v1.y, v1.z, v1.w};
    union { bf16 b[8]; uint4 q; } H, L;
    #pragma unroll
    for (int j = 0; j < 8; j++) {
        bf16 h = __float2bfloat16(vv[j]);
        H.b[j] = h;
        L.b[j] = __float2bfloat16(vv[j] - __bfloat162float(h));
    }
    *(uint4*)(g_Ah + (size_t)m * Dd + d0) = H.q;
    *(uint4*)(g_Al + (size_t)m * Dd + d0) = L.q;
}

// ===================================================================
// conv_w: Wx [d][g] fp32 -> transposed bf16 hi/lo [g][d].
// ===================================================================
__global__ void conv_w(const float* __restrict__ Wx) {
    size_t u = (size_t)blockIdx.x * blockDim.x + threadIdx.x;
    int g  = (int)(u & 4095);
    int d0 = (int)(u >> 12) << 3;
    union { bf16 b[8]; uint4 q; } H, L;
    #pragma unroll
    for (int j = 0; j < 8; j++) {
        float v = Wx[(size_t)(d0 + j) * Gg + g];
        bf16 h = __float2bfloat16(v);
        H.b[j] = h;
        L.b[j] = __float2bfloat16(v - __bfloat162float(h));
    }
    *(uint4*)(g_Bh + (size_t)g * Dd + d0) = H.q;
    *(uint4*)(g_Bl + (size_t)g * Dd + d0) = L.q;
}

// ===================================================================
// tc_gemm: xW = A @ B^T + bias via mma.sync + ldmatrix (UNCHANGED, R16).
// ===================================================================
typedef bf16 SmTile[128][40];    // 10,240 B per tile

__global__ __launch_bounds__(256, 2) void tc_gemm(const float* __restrict__ bias) {
    extern __shared__ bf16 smraw[];
    SmTile* tiles = (SmTile*)smraw;

    const int tid = threadIdx.x;
    const int wid = tid >> 5;
    const int lid = tid & 31;
    const int wm  = wid >> 2;
    const int wn  = wid & 3;
    const int n0  = blockIdx.x * 128;
    const int m0  = blockIdx.y * 128;

    const uint32_t sb0  = smem_u32(smraw);
    const uint32_t offA = ((wm * 64 + (lid & 15)) * 40 + ((lid >> 4) << 3)) * 2;
    const uint32_t offB = ((wn * 32 + (lid & 7) + ((lid >> 4) << 3)) * 40
                           + (((lid >> 3) & 1) << 3)) * 2;

    #define LOADTILES(buf, kt) do { \
        _Pragma("unroll") \
        for (int q = 0; q < 2; q++) { \
            int c  = tid * 2 + q; \
            int r  = c >> 2; \
            int kc = (c & 3) * 8; \
            size_t goff = (size_t)r * Dd + (kt) + kc; \
            cp16(&tiles[(buf)*4 + 0][r][kc], g_Ah + (size_t)m0 * Dd + goff); \
            cp16(&tiles[(buf)*4 + 1][r][kc], g_Al + (size_t)m0 * Dd + goff); \
            cp16(&tiles[(buf)*4 + 2][r][kc], g_Bh + (size_t)n0 * Dd + goff); \
            cp16(&tiles[(buf)*4 + 3][r][kc], g_Bl + (size_t)n0 * Dd + goff); \
        } \
    } while (0)

    float acc[4][4][4];
    #pragma unroll
    for (int mt = 0; mt < 4; mt++)
        #pragma unroll
        for (int nt = 0; nt < 4; nt++)
            #pragma unroll
            for (int e = 0; e < 4; e++) acc[mt][nt][e] = 0.0f;

    LOADTILES(0, 0);
    CP_COMMIT();

    int buf = 0;
    for (int kt = 0; kt < Dd; kt += 32) {
        if (kt + 32 < Dd) LOADTILES(buf ^ 1, kt + 32);
        CP_COMMIT();
        CP_WAIT1();
        __syncthreads();

        const uint32_t baseAh = sb0 + (buf * 4 + 0) * 10240 + offA;
        const uint32_t baseAl = sb0 + (buf * 4 + 1) * 10240 + offA;
        const uint32_t baseBh = sb0 + (buf * 4 + 2) * 10240 + offB;
        const uint32_t baseBl = sb0 + (buf * 4 + 3) * 10240 + offB;

        #pragma unroll
        for (int ks = 0; ks < 32; ks += 16) {
            uint32_t a[4][4], bh[4][2], bl[4][2];

            #pragma unroll
            for (int mt = 0; mt < 4; mt++)
                LDSM4(a[mt][0], a[mt][1], a[mt][2], a[mt][3],
                      baseAh + mt * 1280 + ks * 2);
            #pragma unroll
            for (int p = 0; p < 2; p++) {
                uint32_t t0, t1, t2, t3;
                LDSM4(t0, t1, t2, t3, baseBh + p * 1280 + ks * 2);
                bh[2*p][0] = t0; bh[2*p][1] = t1;
                bh[2*p+1][0] = t2; bh[2*p+1][1] = t3;
                LDSM4(t0, t1, t2, t3, baseBl + p * 1280 + ks * 2);
                bl[2*p][0] = t0; bl[2*p][1] = t1;
                bl[2*p+1][0] = t2; bl[2*p+1][1] = t3;
            }

            #pragma unroll
            for (int mt = 0; mt < 4; mt++)
                #pragma unroll
                for (int nt = 0; nt < 4; nt++)
                    MMA16816(acc[mt][nt], a[mt][0], a[mt][1], a[mt][2], a[mt][3],
                             bh[nt][0], bh[nt][1]);
            #pragma unroll
            for (int mt = 0; mt < 4; mt++)
                #pragma unroll
                for (int nt = 0; nt < 4; nt++)
                    MMA16816(acc[mt][nt], a[mt][0], a[mt][1], a[mt][2], a[mt][3],
                             bl[nt][0], bl[nt][1]);
            #pragma unroll
            for (int mt = 0; mt < 4; mt++)
                LDSM4(a[mt][0], a[mt][1], a[mt][2], a[mt][3],
                      baseAl + mt * 1280 + ks * 2);
            #pragma unroll
            for (int mt = 0; mt < 4; mt++)
                #pragma unroll
                for (int nt = 0; nt < 4; nt++)
                    MMA16816(acc[mt][nt], a[mt][0], a[mt][1], a[mt][2], a[mt][3],
                             bh[nt][0], bh[nt][1]);
        }
        __syncthreads();
        buf ^= 1;
    }

    const int grp = lid >> 2;
    const int tg  = lid & 3;
    #pragma unroll
    for (int mt = 0; mt < 4; mt++) {
        int mrow = m0 + wm * 64 + mt * 16 + grp;
        #pragma unroll
        for (int nt = 0; nt < 4; nt++) {
            int col = n0 + wn * 32 + nt * 8 + tg * 2;
            float2 bv = *(const float2*)(bias + col);
            float2 v0 = make_float2(acc[mt][nt][0] + bv.x, acc[mt][nt][1] + bv.y);
            float2 v1 = make_float2(acc[mt][nt][2] + bv.x, acc[mt][nt][3] + bv.y);
            *(float2*)(g_xw + (size_t)mrow * Gg + col) = v0;
            *(float2*)(g_xw + (size_t)(mrow + 8) * Gg + col) = v1;
        }
    }
    #undef LOADTILES
}

// ===================================================================
// Kernel 2: persistent LSTM recurrence — per-warp staging, no named
// barriers in the chunk loop.
// Structural fact: warp wg reads ONLY its own 16 A-rows per chunk; B is
// resident Wh smem. So each warp stages its 16 rows x k16 (hi+lo = 1KB)
// into a PRIVATE 3-buffer ring via cp.async; ordering = wait_group 1 +
// __syncwarp (same-warp producer/consumer). Zero cross-warp sync until
// the partials/gate stage. Quarter spin is per-warp (lane 0 + syncwarp).
// WAR safety (unchanged from R14): gate writes to buffer (t+1)&1 occur
// after __syncthreads that follows all 4 groups' spins on step t-1
// quarters (union = all 128 CTAs published t-1 => all finished reading
// that buffer). Partials in a dedicated region again.
// smem: Wh 132096 + 16 warps x 3KB ring + partials 33792 = 215040 B.
// ===================================================================
#define WH_STRIDE 1032

__global__ __launch_bounds__(512, 1) void lstm_persist(const float* __restrict__ Wh,
                                                       float* __restrict__ out) {
    extern __shared__ char smc[];
    bf16*  Whh = (bf16*)smc;                          // [32][1032]
    bf16*  Whl = Whh + 32 * WH_STRIDE;                // [32][1032]
    char*  wS  = smc + 132096;                        // 16 warps x 3 bufs x 1024 B
    float* pS  = (float*)(smc + 132096 + 49152);      // 4 groups x [64][33]

    const int tid = threadIdx.x;
    const int j0  = blockIdx.x * 8;
    const int quarter = blockIdx.x >> 5;
    const int w   = tid >> 5;               // warp 0..15
    const int g   = w >> 2;                 // K-split group 0..3
    const int wg  = w & 3;                  // m-tile within group
    const int lid = tid & 31;
    const int grp = lid >> 2;               // 0..7
    const int tg  = lid & 3;                // 0..3
    const int n   = tid >> 3;               // gate-stage row 0..63
    const int jj  = tid & 7;                // gate-stage col 0..7

    // ---- convert Wh slice -> smem bf16 hi/lo [c][k], c = gate*8+jj ----
    {
        int c  = tid & 31;
        int gate = c >> 3, cj = c & 7;
        const float* wp = Wh + (size_t)gate * Hh + j0 + cj;
        for (int k = tid >> 5; k < Hh; k += 16) {
            float wv = wp[(size_t)k * Gg];
            bf16 wh = __float2bfloat16(wv);
            Whh[c * WH_STRIDE + k] = wh;
            Whl[c * WH_STRIDE + k] = __float2bfloat16(wv - __bfloat162float(wh));
        }
    }
    __syncthreads();

    float c_reg = 0.0f;
    const int kbase   = g * 256;
    const int rowbase = wg * 16;             // this warp's 16 batch rows
    char*  mybuf  = wS + w * 3072;           // private 3-buf ring
    float* mypart = pS + g * 2112;

    // per-lane load job constants: jobs lid and lid+32 of 64
    // job j: half=j>>5, r=(j&31)>>1, seg=j&1
    const int r0c = lid >> 1, s0c = lid & 1;            // job lid (half 0)
    const int r1c = r0c,      s1c = s0c;                // job lid+32 (half 1)

    for (int t = 0; t < Ts; t++) {
        const bf16* hbh = g_hbh[t & 1];
        const bf16* hbl = g_hbl[t & 1];
        bf16* hoh = g_hbh[(t + 1) & 1];
        bf16* hol = g_hbl[(t + 1) & 1];

        // prefetch xW addends (DRAM latency overlaps the spin below)
        const float* xwp = g_xw + ((size_t)t * Nb + n) * Gg + j0 + jj;
        float xi = xwp[0], xf = xwp[Hh], xo = xwp[2 * Hh], xg = xwp[3 * Hh];

        // per-WARP input-ready wait: quarter g published step-t input
        if (t > 0) {
            if (lid == 0) {
                int v;
                do {
                    asm volatile("ld.acquire.gpu.global.b32 %0, [%1];"
                                 : "=r"(v) : "l"(&g_barq[t - 1][g]) : "memory");
                } while (v < 32);
            }
            __syncwarp();
        }

        float acc[4][4];
        #pragma unroll
        for (int nt = 0; nt < 4; nt++)
            #pragma unroll
            for (int e = 0; e < 4; e++) acc[nt][e] = 0.0f;

        // per-warp chunk stage: 2 cp16 per lane (hi job, lo job)
        #define LOADW(dst, ch) do { \
            const bf16* s0 = hbh + (size_t)(rowbase + r0c) * Hh + kbase + (ch) * 16 + s0c * 8; \
            const bf16* s1 = hbl + (size_t)(rowbase + r1c) * Hh + kbase + (ch) * 16 + s1c * 8; \
            cp16((dst) + r0c * 32 + s0c * 16, s0); \
            cp16((dst) + 512 + r1c * 32 + s1c * 16, s1); \
        } while (0)

        // prologue: chunks 0,1 into ring slots 0,1
        LOADW(mybuf + 0 * 1024, 0); CP_COMMIT();
        LOADW(mybuf + 1 * 1024, 1); CP_COMMIT();

        int slot = 0;
        #pragma unroll 1
        for (int ch = 0; ch < 16; ch++) {
            CP_WAIT1();          // chunk ch complete (1 outstanding allowed)
            __syncwarp();        // all lanes' cp.asyncs for ch visible warp-wide

            const bf16* Ah = (const bf16*)(mybuf + slot * 1024);   // [16][16]
            const bf16* Al = Ah + 256;
            const int kk = kbase + ch * 16 + tg * 2;               // B k index

            uint32_t ah0 = *(const uint32_t*)&Ah[grp * 16 + tg * 2];
            uint32_t ah1 = *(const uint32_t*)&Ah[(grp + 8) * 16 + tg * 2];
            uint32_t ah2 = *(const uint32_t*)&Ah[grp * 16 + tg * 2 + 8];
            uint32_t ah3 = *(const uint32_t*)&Ah[(grp + 8) * 16 + tg * 2 + 8];
            uint32_t al0 = *(const uint32_t*)&Al[grp * 16 + tg * 2];
            uint32_t al1 = *(const uint32_t*)&Al[(grp + 8) * 16 + tg * 2];
            uint32_t al2 = *(const uint32_t*)&Al[grp * 16 + tg * 2 + 8];
            uint32_t al3 = *(const uint32_t*)&Al[(grp + 8) * 16 + tg * 2 + 8];

            #pragma unroll
            for (int nt = 0; nt < 4; nt++) {
                int br = nt * 8 + grp;
                uint32_t bh0 = *(const uint32_t*)&Whh[br * WH_STRIDE + kk];
                uint32_t bh1 = *(const uint32_t*)&Whh[br * WH_STRIDE + kk + 8];
                uint32_t bl0 = *(const uint32_t*)&Whl[br * WH_STRIDE + kk];
                uint32_t bl1 = *(const uint32_t*)&Whl[br * WH_STRIDE + kk + 8];
                MMA16816(acc[nt], ah0, ah1, ah2, ah3, bh0, bh1);
                MMA16816(acc[nt], ah0, ah1, ah2, ah3, bl0, bl1);
                MMA16816(acc[nt], al0, al1, al2, al3, bh0, bh1);
            }

            // stage chunk ch+2 into slot (ch+2)%3 = (slot+2)%3; its previous
            // reader was compute(ch-1), already done in program order.
            if (ch < 14) {
                int ns = slot + 2; if (ns >= 3) ns -= 3;
                LOADW(mybuf + ns * 1024, ch + 2);
            }
            CP_COMMIT();         // empty groups in tail keep the wait count exact
            if (++slot == 3) slot = 0;
        }
        #undef LOADW

        // write K-split partials to the dedicated region ([64][33])
        const int ar = wg * 16 + grp;
        #pragma unroll
        for (int nt = 0; nt < 4; nt++) {
            int col = nt * 8 + tg * 2;
            float* p0 = mypart + ar * 33 + col;
            p0[0] = acc[nt][0]; p0[1] = acc[nt][1];
            float* p1 = mypart + (ar + 8) * 33 + col;
            p1[0] = acc[nt][2]; p1[1] = acc[nt][3];
        }
        __syncthreads();   // all groups' partials visible; orders all spins
                           // before the h writes below

        // gates: reduce 4 partials + xW, update c (register), emit h
        float Ai = xi, Af = xf, Ao = xo, Ag = xg;
        #pragma unroll
        for (int gr = 0; gr < 4; gr++) {
            const float* p = pS + gr * 2112 + n * 33;
            Ai += p[jj]; Af += p[8 + jj]; Ao += p[16 + jj]; Ag += p[24 + jj];
        }
        float ig = __fdividef(1.0f, 1.0f + __expf(-Ai));
        float fg = __fdividef(1.0f, 1.0f + __expf(-Af));
        float og = __fdividef(1.0f, 1.0f + __expf(-Ao));
        float gg = __fdividef(2.0f, 1.0f + __expf(-2.0f * Ag)) - 1.0f;
        c_reg = fg * c_reg + ig * gg;
        float th = __fdividef(2.0f, 1.0f + __expf(-2.0f * c_reg)) - 1.0f;
        float hv = og * th;

        bf16 hh = __float2bfloat16(hv);
        hoh[n * Hh + j0 + jj] = hh;
        hol[n * Hh + j0 + jj] = __float2bfloat16(hv - __bfloat162float(hh));

        // publish: this CTA's h columns for step t+1 are ready
        __syncthreads();                      // all 512 threads' h writes done
        if (tid == 0) {
            __threadfence();
            atomicAdd(&g_barq[t][quarter], 1);
        }

        // out[] store off the critical chain (nobody else reads it)
        out[((size_t)n * Ts + t) * Hh + j0 + jj] = hv;
    }
}

// ===================================================================
// Host launch
// ===================================================================
extern "C" void kernel_launch(void* const* d_in, const int* in_sizes, int n_in,
                              void* d_out, int out_size) {
    const float* x  = (const float*)d_in[0];   // (64, 512, 1024)
    const float* h0 = (const float*)d_in[1];   // (64, 1024)
    const float* Wx = (const float*)d_in[2];   // (1024, 4096)
    const float* Wh = (const float*)d_in[3];   // (1024, 4096)
    const float* b  = (const float*)d_in[4];   // (4096)
    float* out = (float*)d_out;                // (64, 512, 1024)

    cudaFuncSetAttribute(lstm_persist, cudaFuncAttributeMaxDynamicSharedMemorySize, 215040);
    cudaFuncSetAttribute(tc_gemm, cudaFuncAttributeMaxDynamicSharedMemorySize, 81920);

    prep<<<64, 256>>>(h0);
    conv_x<<<16384, 256>>>(x);
    conv_w<<<2048, 256>>>(Wx);

    dim3 gg(Gg / 128, (Nb * Ts) / 128);        // (32, 256) — N fastest for A L2 reuse
    tc_gemm<<<gg, 256, 81920>>>(b);

    lstm_persist<<<128, 512, 215040>>>(Wh, out);
}